// round 1
// baseline (speedup 1.0000x reference)
#include <cuda_runtime.h>
#include <cstddef>

#define NC 100000
#define NE 200000
#define NV 150000

// ---------------- scratch (static device globals; no allocations) ----------------
__device__ float g_agg0[NC * 64];   // entity->claim aggregate (layer1), reused layer2
__device__ float g_agg1[NC * 64];   // evidence->claim aggregate (layer1), reused layer2
__device__ float g_agg2[NE * 64];   // claim->entity aggregate
__device__ float g_agg3[NV * 64];   // claim->evidence aggregate
__device__ float g_cnt0[NC];
__device__ float g_cnt1[NC];
__device__ float g_cnt2[NE];
__device__ float g_cnt3[NV];
__device__ float g_h1c[NC * 64];
__device__ float g_h1e[NE * 64];
__device__ float g_h1v[NV * 64];
__device__ float g_Wr1c[64 * 64];   // Wr1[0] + Wr1[1]
__device__ float g_b1c[64];         // bl1[0] + bl1[1]
__device__ float g_u0[64 * 2];      // Wl2[0] @ Wc
__device__ float g_u1[64 * 2];      // Wl2[1] @ Wc
__device__ float g_ur[64 * 2];      // (Wr2[0]+Wr2[1]) @ Wc
__device__ float g_b2[2];           // (bl2[0]+bl2[1]) @ Wc + bc

// ---------------- tiny weight prep ----------------
__global__ void prep_kernel(const float* __restrict__ Wr1, const float* __restrict__ bl1,
                            const float* __restrict__ Wl2, const float* __restrict__ bl2,
                            const float* __restrict__ Wr2, const float* __restrict__ Wc,
                            const float* __restrict__ bc)
{
    int tid = threadIdx.x;
    for (int idx = tid; idx < 4096; idx += 256)
        g_Wr1c[idx] = Wr1[idx] + Wr1[4096 + idx];
    if (tid < 64) g_b1c[tid] = bl1[tid] + bl1[64 + tid];
    if (tid < 128) {
        int i = tid >> 1, c = tid & 1;
        float s0 = 0.f, s1 = 0.f, sr = 0.f;
        for (int j = 0; j < 64; j++) {
            float wc = Wc[j * 2 + c];
            s0 += Wl2[i * 64 + j] * wc;
            s1 += Wl2[4096 + i * 64 + j] * wc;
            sr += (Wr2[i * 64 + j] + Wr2[4096 + i * 64 + j]) * wc;
        }
        g_u0[tid] = s0; g_u1[tid] = s1; g_ur[tid] = sr;
    }
    if (tid < 2) {
        float s = bc[tid];
        for (int j = 0; j < 64; j++) s += (bl2[j] + bl2[64 + j]) * Wc[j * 2 + tid];
        g_b2[tid] = s;
    }
}

// ---------------- edge scatter: mean-aggregate accumulation ----------------
// 16 threads per edge; each thread moves one float4 (row is 64 floats = 16 float4).
__global__ void scatter_kernel(const float4* __restrict__ xsrc,
                               const int* __restrict__ esrc,
                               const int* __restrict__ edst,
                               float4* __restrict__ agg,
                               float* __restrict__ cnt,
                               int E)
{
    int t = blockIdx.x * blockDim.x + threadIdx.x;
    int e = t >> 4;
    if (e >= E) return;
    int j = t & 15;
    int s = __ldg(esrc + e);
    int d = __ldg(edst + e);
    float4 v = __ldg(xsrc + (size_t)s * 16 + j);
    float4* p = agg + (size_t)d * 16 + j;
    asm volatile("red.global.add.v4.f32 [%0], {%1,%2,%3,%4};"
                 :: "l"(p), "f"(v.x), "f"(v.y), "f"(v.z), "f"(v.w) : "memory");
    if (j == 0) atomicAdd(cnt + d, 1.0f);
}

// ---------------- fused mean-divide + (NMEAN+1)-way 64x64 GEMM + bias + ReLU ----------------
// Block: 256 threads handles 64 rows. Thread (cg,rg): 4 cols x 4 rows register tile.
template <int NMEAN, bool RELU>
__global__ void transform_kernel(const float* __restrict__ agg0, const float* __restrict__ cnt0,
                                 const float* __restrict__ agg1, const float* __restrict__ cnt1,
                                 const float* __restrict__ x,
                                 const float* __restrict__ W0, const float* __restrict__ W1,
                                 const float* __restrict__ Wr,
                                 const float* __restrict__ bias,
                                 float* __restrict__ out, int n)
{
    __shared__ __align__(16) float Ws[64][68];
    __shared__ __align__(16) float As[64][68];
    int tid = threadIdx.x;
    int row0 = blockIdx.x * 64;
    int cg = tid & 15, rg = tid >> 4;
    int c0 = cg * 4, r0 = rg * 4;

    float acc[4][4];
#pragma unroll
    for (int ci = 0; ci < 4; ci++) {
        float b = bias[c0 + ci];
#pragma unroll
        for (int ri = 0; ri < 4; ri++) acc[ri][ci] = b;
    }

    for (int p = 0; p <= NMEAN; ++p) {
        const float* inp;
        const float* W;
        const float* cnt;
        if (p == 0 && NMEAN >= 1)      { inp = agg0; W = W0; cnt = cnt0; }
        else if (p == 1 && NMEAN == 2) { inp = agg1; W = W1; cnt = cnt1; }
        else                           { inp = x;    W = Wr; cnt = nullptr; }

#pragma unroll
        for (int i = 0; i < 16; i++) {
            int idx = tid + i * 256;
            Ws[idx >> 6][idx & 63] = W[idx];
        }
#pragma unroll
        for (int i = 0; i < 16; i++) {
            int idx = tid + i * 256;
            int r = idx >> 6, c = idx & 63;
            int row = row0 + r;
            float v = 0.f;
            if (row < n) {
                v = inp[(size_t)row * 64 + c];
                if (cnt) {
                    float cv = cnt[row];
                    v *= 1.0f / fmaxf(cv, 1.0f);
                }
            }
            As[r][c] = v;
        }
        __syncthreads();

#pragma unroll
        for (int k = 0; k < 64; k++) {
            float4 wv = *(const float4*)&Ws[k][c0];
            float a0 = As[r0 + 0][k];
            float a1 = As[r0 + 1][k];
            float a2 = As[r0 + 2][k];
            float a3 = As[r0 + 3][k];
            acc[0][0] += a0 * wv.x; acc[0][1] += a0 * wv.y; acc[0][2] += a0 * wv.z; acc[0][3] += a0 * wv.w;
            acc[1][0] += a1 * wv.x; acc[1][1] += a1 * wv.y; acc[1][2] += a1 * wv.z; acc[1][3] += a1 * wv.w;
            acc[2][0] += a2 * wv.x; acc[2][1] += a2 * wv.y; acc[2][2] += a2 * wv.z; acc[2][3] += a2 * wv.w;
            acc[3][0] += a3 * wv.x; acc[3][1] += a3 * wv.y; acc[3][2] += a3 * wv.z; acc[3][3] += a3 * wv.w;
        }
        __syncthreads();
    }

#pragma unroll
    for (int ri = 0; ri < 4; ri++) {
        int row = row0 + r0 + ri;
        if (row < n) {
            float4 o;
            o.x = RELU ? fmaxf(acc[ri][0], 0.f) : acc[ri][0];
            o.y = RELU ? fmaxf(acc[ri][1], 0.f) : acc[ri][1];
            o.z = RELU ? fmaxf(acc[ri][2], 0.f) : acc[ri][2];
            o.w = RELU ? fmaxf(acc[ri][3], 0.f) : acc[ri][3];
            *(float4*)&out[(size_t)row * 64 + c0] = o;
        }
    }
}

// ---------------- final: folded layer-2 linear + classifier on gathered claims ----------------
__global__ void final_kernel(const float4* __restrict__ agg0, const float* __restrict__ cnt0,
                             const float4* __restrict__ agg1, const float* __restrict__ cnt1,
                             const float4* __restrict__ h1c,
                             const int* __restrict__ bidx,
                             float* __restrict__ out, int B)
{
    int b = blockIdx.x * blockDim.x + threadIdx.x;
    if (b >= B) return;
    int i = __ldg(bidx + b);
    float inv0 = 1.0f / fmaxf(cnt0[i], 1.0f);
    float inv1 = 1.0f / fmaxf(cnt1[i], 1.0f);
    float acc0 = g_b2[0], acc1 = g_b2[1];
#pragma unroll
    for (int q = 0; q < 16; q++) {
        float4 m0 = __ldg(agg0 + (size_t)i * 16 + q);
        float4 m1 = __ldg(agg1 + (size_t)i * 16 + q);
        float4 h  = __ldg(h1c  + (size_t)i * 16 + q);
        float m0a[4] = {m0.x, m0.y, m0.z, m0.w};
        float m1a[4] = {m1.x, m1.y, m1.z, m1.w};
        float ha[4]  = {h.x,  h.y,  h.z,  h.w};
#pragma unroll
        for (int t = 0; t < 4; t++) {
            int k = q * 4 + t;
            acc0 += m0a[t] * inv0 * g_u0[k * 2 + 0]
                  + m1a[t] * inv1 * g_u1[k * 2 + 0]
                  + ha[t]         * g_ur[k * 2 + 0];
            acc1 += m0a[t] * inv0 * g_u0[k * 2 + 1]
                  + m1a[t] * inv1 * g_u1[k * 2 + 1]
                  + ha[t]         * g_ur[k * 2 + 1];
        }
    }
    out[(size_t)b * 2 + 0] = acc0;
    out[(size_t)b * 2 + 1] = acc1;
}

// ---------------- launch ----------------
extern "C" void kernel_launch(void* const* d_in, const int* in_sizes, int n_in,
                              void* d_out, int out_size)
{
    const float* x_claim  = (const float*)d_in[0];
    const float* x_entity = (const float*)d_in[1];
    const float* x_evid   = (const float*)d_in[2];
    const int*   ei       = (const int*)d_in[3];     // [4, 2, E]
    const int*   bidx     = (const int*)d_in[4];     // [B]
    const float* Wl1      = (const float*)d_in[5];   // [4,64,64]
    const float* bl1      = (const float*)d_in[6];   // [4,64]
    const float* Wr1      = (const float*)d_in[7];   // [4,64,64]
    const float* Wl2      = (const float*)d_in[8];
    const float* bl2      = (const float*)d_in[9];
    const float* Wr2      = (const float*)d_in[10];
    const float* Wc       = (const float*)d_in[11];  // [64,2]
    const float* bc       = (const float*)d_in[12];  // [2]
    float* out = (float*)d_out;

    const int E  = in_sizes[3] / 8;   // 4 * 2 * E elements
    const int B  = in_sizes[4];
    const int nc = in_sizes[0] / 64;
    const int ne = in_sizes[1] / 64;
    const int nv = in_sizes[2] / 64;

    float *agg0, *agg1, *agg2, *agg3, *cnt0, *cnt1, *cnt2, *cnt3, *h1c, *h1e, *h1v;
    cudaGetSymbolAddress((void**)&agg0, g_agg0);
    cudaGetSymbolAddress((void**)&agg1, g_agg1);
    cudaGetSymbolAddress((void**)&agg2, g_agg2);
    cudaGetSymbolAddress((void**)&agg3, g_agg3);
    cudaGetSymbolAddress((void**)&cnt0, g_cnt0);
    cudaGetSymbolAddress((void**)&cnt1, g_cnt1);
    cudaGetSymbolAddress((void**)&cnt2, g_cnt2);
    cudaGetSymbolAddress((void**)&cnt3, g_cnt3);
    cudaGetSymbolAddress((void**)&h1c, g_h1c);
    cudaGetSymbolAddress((void**)&h1e, g_h1e);
    cudaGetSymbolAddress((void**)&h1v, g_h1v);

    float *Wr1c, *b1c;
    cudaGetSymbolAddress((void**)&Wr1c, g_Wr1c);
    cudaGetSymbolAddress((void**)&b1c, g_b1c);

    // prep folded weights
    prep_kernel<<<1, 256>>>(Wr1, bl1, Wl2, bl2, Wr2, Wc, bc);

    // zero layer-1 accumulators
    cudaMemsetAsync(agg0, 0, (size_t)nc * 64 * sizeof(float));
    cudaMemsetAsync(agg1, 0, (size_t)nc * 64 * sizeof(float));
    cudaMemsetAsync(agg2, 0, (size_t)ne * 64 * sizeof(float));
    cudaMemsetAsync(agg3, 0, (size_t)nv * 64 * sizeof(float));
    cudaMemsetAsync(cnt0, 0, (size_t)nc * sizeof(float));
    cudaMemsetAsync(cnt1, 0, (size_t)nc * sizeof(float));
    cudaMemsetAsync(cnt2, 0, (size_t)ne * sizeof(float));
    cudaMemsetAsync(cnt3, 0, (size_t)nv * sizeof(float));

    const int sthreads = 256;
    const int sblocks = (E * 16 + sthreads - 1) / sthreads;
    const size_t e2 = (size_t)2 * E;

    // layer-1 scatter: one kernel per edge type (keeps working set L2-resident)
    scatter_kernel<<<sblocks, sthreads>>>((const float4*)x_entity, ei + 0 * e2, ei + 0 * e2 + E,
                                          (float4*)agg0, cnt0, E);
    scatter_kernel<<<sblocks, sthreads>>>((const float4*)x_evid,   ei + 1 * e2, ei + 1 * e2 + E,
                                          (float4*)agg1, cnt1, E);
    scatter_kernel<<<sblocks, sthreads>>>((const float4*)x_claim,  ei + 2 * e2, ei + 2 * e2 + E,
                                          (float4*)agg2, cnt2, E);
    scatter_kernel<<<sblocks, sthreads>>>((const float4*)x_claim,  ei + 3 * e2, ei + 3 * e2 + E,
                                          (float4*)agg3, cnt3, E);

    // layer-1 transforms (+ReLU)
    transform_kernel<2, true><<<(nc + 63) / 64, 256>>>(agg0, cnt0, agg1, cnt1, x_claim,
                                                       Wl1 + 0 * 4096, Wl1 + 1 * 4096, Wr1c, b1c,
                                                       h1c, nc);
    transform_kernel<1, true><<<(ne + 63) / 64, 256>>>(agg2, cnt2, nullptr, nullptr, x_entity,
                                                       Wl1 + 2 * 4096, nullptr, Wr1 + 2 * 4096, bl1 + 128,
                                                       h1e, ne);
    transform_kernel<1, true><<<(nv + 63) / 64, 256>>>(agg3, cnt3, nullptr, nullptr, x_evid,
                                                       Wl1 + 3 * 4096, nullptr, Wr1 + 3 * 4096, bl1 + 192,
                                                       h1v, nv);

    // layer-2: only claim-destination edge types matter for the output
    cudaMemsetAsync(agg0, 0, (size_t)nc * 64 * sizeof(float));
    cudaMemsetAsync(agg1, 0, (size_t)nc * 64 * sizeof(float));
    cudaMemsetAsync(cnt0, 0, (size_t)nc * sizeof(float));
    cudaMemsetAsync(cnt1, 0, (size_t)nc * sizeof(float));

    scatter_kernel<<<sblocks, sthreads>>>((const float4*)h1e, ei + 0 * e2, ei + 0 * e2 + E,
                                          (float4*)agg0, cnt0, E);
    scatter_kernel<<<sblocks, sthreads>>>((const float4*)h1v, ei + 1 * e2, ei + 1 * e2 + E,
                                          (float4*)agg1, cnt1, E);

    // folded layer-2 linear + classifier, gathered on batch indices
    final_kernel<<<(B + 255) / 256, 256>>>((const float4*)agg0, cnt0, (const float4*)agg1, cnt1,
                                           (const float4*)h1c, bidx, out, B);
}

// round 2
// speedup vs baseline: 1.0379x; 1.0379x over previous
#include <cuda_runtime.h>
#include <cstddef>

#define NC 100000
#define NE 200000
#define NV 150000

// ---------------- consolidated zeroed scratch (single memset) ----------------
#define O_AGG0  0
#define O_AGG1  (NC*64)
#define O_AGG2  (2*NC*64)
#define O_AGG3  (2*NC*64 + NE*64)
#define O_AGGL0 (2*NC*64 + NE*64 + NV*64)
#define O_AGGL1 (3*NC*64 + NE*64 + NV*64)
#define O_CNT0  (4*NC*64 + NE*64 + NV*64)
#define O_CNT1  (O_CNT0 + NC)
#define O_CNT2  (O_CNT1 + NC)
#define O_CNT3  (O_CNT2 + NE)
#define ZTOT    (O_CNT3 + NV)

__device__ float g_zero[ZTOT];
__device__ float g_h1c[NC * 64];
__device__ float g_h1e[NE * 64];
__device__ float g_h1v[NV * 64];
__device__ float g_Wr1c[64 * 64];   // Wr1[0] + Wr1[1]
__device__ float g_b1c[64];         // bl1[0] + bl1[1]
__device__ float g_u0[64 * 2];      // Wl2[0] @ Wc
__device__ float g_u1[64 * 2];      // Wl2[1] @ Wc
__device__ float g_ur[64 * 2];      // (Wr2[0]+Wr2[1]) @ Wc
__device__ float g_b2[2];           // (bl2[0]+bl2[1]) @ Wc + bc

// ---------------- f32x2 packed-FMA helpers ----------------
__device__ __forceinline__ unsigned long long fma2(unsigned long long a,
                                                   unsigned long long b,
                                                   unsigned long long c) {
    unsigned long long d;
    asm("fma.rn.f32x2 %0, %1, %2, %3;" : "=l"(d) : "l"(a), "l"(b), "l"(c));
    return d;
}
__device__ __forceinline__ unsigned long long pack2(float lo, float hi) {
    unsigned long long d;
    asm("mov.b64 %0, {%1, %2};" : "=l"(d) : "f"(lo), "f"(hi));
    return d;
}
__device__ __forceinline__ unsigned long long dup2(float v) {
    unsigned long long d;
    asm("mov.b64 %0, {%1, %1};" : "=l"(d) : "f"(v));
    return d;
}
__device__ __forceinline__ void unpack2(unsigned long long v, float& lo, float& hi) {
    asm("mov.b64 {%0, %1}, %2;" : "=f"(lo), "=f"(hi) : "l"(v));
}

// ---------------- tiny weight prep ----------------
__global__ void prep_kernel(const float* __restrict__ Wr1, const float* __restrict__ bl1,
                            const float* __restrict__ Wl2, const float* __restrict__ bl2,
                            const float* __restrict__ Wr2, const float* __restrict__ Wc,
                            const float* __restrict__ bc)
{
    int tid = threadIdx.x;
    for (int idx = tid; idx < 4096; idx += 256)
        g_Wr1c[idx] = Wr1[idx] + Wr1[4096 + idx];
    if (tid < 64) g_b1c[tid] = bl1[tid] + bl1[64 + tid];
    if (tid < 128) {
        int i = tid >> 1, c = tid & 1;
        float s0 = 0.f, s1 = 0.f, sr = 0.f;
        for (int j = 0; j < 64; j++) {
            float wc = Wc[j * 2 + c];
            s0 += Wl2[i * 64 + j] * wc;
            s1 += Wl2[4096 + i * 64 + j] * wc;
            sr += (Wr2[i * 64 + j] + Wr2[4096 + i * 64 + j]) * wc;
        }
        g_u0[tid] = s0; g_u1[tid] = s1; g_ur[tid] = sr;
    }
    if (tid < 2) {
        float s = bc[tid];
        for (int j = 0; j < 64; j++) s += (bl2[j] + bl2[64 + j]) * Wc[j * 2 + tid];
        g_b2[tid] = s;
    }
}

// ---------------- merged multi-type edge scatter ----------------
struct SCArgs {
    const float4* src[4];
    float4*       agg[4];
    float*        cnt[4];
    const int*    es[4];
    const int*    ed[4];
};

template <bool COUNT>
__global__ void scatter_multi(SCArgs a, int E)
{
    int ty = blockIdx.y;
    int t = blockIdx.x * blockDim.x + threadIdx.x;
    int e = t >> 4;
    if (e >= E) return;
    int j = t & 15;
    int s = __ldg(a.es[ty] + e);
    int d = __ldg(a.ed[ty] + e);
    float4 v = __ldg(a.src[ty] + (size_t)s * 16 + j);
    float4* p = a.agg[ty] + (size_t)d * 16 + j;
    asm volatile("red.global.add.v4.f32 [%0], {%1,%2,%3,%4};"
                 :: "l"(p), "f"(v.x), "f"(v.y), "f"(v.z), "f"(v.w) : "memory");
    if (COUNT && j == 0) atomicAdd(a.cnt[ty] + d, 1.0f);
}

// ---------------- fused mean + (NMEAN+1)-way 64x64 GEMM + bias + ReLU (f32x2) ----------------
template <int NMEAN, bool RELU>
__global__ __launch_bounds__(256)
void transform_kernel(const float* __restrict__ agg0, const float* __restrict__ cnt0,
                      const float* __restrict__ agg1, const float* __restrict__ cnt1,
                      const float* __restrict__ x,
                      const float* __restrict__ W0, const float* __restrict__ W1,
                      const float* __restrict__ Wr,
                      const float* __restrict__ bias,
                      float* __restrict__ out, int n)
{
    __shared__ __align__(16) float Ws[64][68];
    __shared__ __align__(16) float As[64][68];
    int tid = threadIdx.x;
    int row0 = blockIdx.x * 64;
    int cg = tid & 15, rg = tid >> 4;
    int c0 = cg * 4, r0 = rg * 4;

    unsigned long long b01 = pack2(bias[c0], bias[c0 + 1]);
    unsigned long long b23 = pack2(bias[c0 + 2], bias[c0 + 3]);
    unsigned long long acc[4][2];
#pragma unroll
    for (int ri = 0; ri < 4; ri++) { acc[ri][0] = b01; acc[ri][1] = b23; }

    for (int p = 0; p <= NMEAN; ++p) {
        const float* inp;
        const float* W;
        const float* cnt;
        if (p == 0 && NMEAN >= 1)      { inp = agg0; W = W0; cnt = cnt0; }
        else if (p == 1 && NMEAN == 2) { inp = agg1; W = W1; cnt = cnt1; }
        else                           { inp = x;    W = Wr; cnt = nullptr; }

#pragma unroll
        for (int i = 0; i < 16; i++) {
            int idx = tid + i * 256;
            Ws[idx >> 6][idx & 63] = W[idx];
        }
#pragma unroll
        for (int i = 0; i < 16; i++) {
            int idx = tid + i * 256;
            int r = idx >> 6, c = idx & 63;
            int row = row0 + r;
            float v = 0.f;
            if (row < n) {
                v = inp[(size_t)row * 64 + c];
                if (cnt) {
                    float cv = cnt[row];
                    v *= 1.0f / fmaxf(cv, 1.0f);
                }
            }
            As[r][c] = v;
        }
        __syncthreads();

#pragma unroll
        for (int k = 0; k < 64; k++) {
            unsigned long long w01 = *(const unsigned long long*)&Ws[k][c0];
            unsigned long long w23 = *(const unsigned long long*)&Ws[k][c0 + 2];
            unsigned long long a0 = dup2(As[r0 + 0][k]);
            unsigned long long a1 = dup2(As[r0 + 1][k]);
            unsigned long long a2 = dup2(As[r0 + 2][k]);
            unsigned long long a3 = dup2(As[r0 + 3][k]);
            acc[0][0] = fma2(a0, w01, acc[0][0]); acc[0][1] = fma2(a0, w23, acc[0][1]);
            acc[1][0] = fma2(a1, w01, acc[1][0]); acc[1][1] = fma2(a1, w23, acc[1][1]);
            acc[2][0] = fma2(a2, w01, acc[2][0]); acc[2][1] = fma2(a2, w23, acc[2][1]);
            acc[3][0] = fma2(a3, w01, acc[3][0]); acc[3][1] = fma2(a3, w23, acc[3][1]);
        }
        __syncthreads();
    }

#pragma unroll
    for (int ri = 0; ri < 4; ri++) {
        int row = row0 + r0 + ri;
        if (row < n) {
            float4 o;
            unpack2(acc[ri][0], o.x, o.y);
            unpack2(acc[ri][1], o.z, o.w);
            if (RELU) {
                o.x = fmaxf(o.x, 0.f); o.y = fmaxf(o.y, 0.f);
                o.z = fmaxf(o.z, 0.f); o.w = fmaxf(o.w, 0.f);
            }
            *(float4*)&out[(size_t)row * 64 + c0] = o;
        }
    }
}

// ---------------- final: folded layer-2 linear + classifier on gathered claims ----------------
__global__ void final_kernel(const float4* __restrict__ agg0, const float* __restrict__ cnt0,
                             const float4* __restrict__ agg1, const float* __restrict__ cnt1,
                             const float4* __restrict__ h1c,
                             const int* __restrict__ bidx,
                             float* __restrict__ out, int B)
{
    int b = blockIdx.x * blockDim.x + threadIdx.x;
    if (b >= B) return;
    int i = __ldg(bidx + b);
    float inv0 = 1.0f / fmaxf(cnt0[i], 1.0f);
    float inv1 = 1.0f / fmaxf(cnt1[i], 1.0f);
    float acc0 = g_b2[0], acc1 = g_b2[1];
#pragma unroll
    for (int q = 0; q < 16; q++) {
        float4 m0 = __ldg(agg0 + (size_t)i * 16 + q);
        float4 m1 = __ldg(agg1 + (size_t)i * 16 + q);
        float4 h  = __ldg(h1c  + (size_t)i * 16 + q);
        float m0a[4] = {m0.x, m0.y, m0.z, m0.w};
        float m1a[4] = {m1.x, m1.y, m1.z, m1.w};
        float ha[4]  = {h.x,  h.y,  h.z,  h.w};
#pragma unroll
        for (int t = 0; t < 4; t++) {
            int k = q * 4 + t;
            acc0 += m0a[t] * inv0 * g_u0[k * 2 + 0]
                  + m1a[t] * inv1 * g_u1[k * 2 + 0]
                  + ha[t]         * g_ur[k * 2 + 0];
            acc1 += m0a[t] * inv0 * g_u0[k * 2 + 1]
                  + m1a[t] * inv1 * g_u1[k * 2 + 1]
                  + ha[t]         * g_ur[k * 2 + 1];
        }
    }
    out[(size_t)b * 2 + 0] = acc0;
    out[(size_t)b * 2 + 1] = acc1;
}

// ---------------- launch ----------------
extern "C" void kernel_launch(void* const* d_in, const int* in_sizes, int n_in,
                              void* d_out, int out_size)
{
    const float* x_claim  = (const float*)d_in[0];
    const float* x_entity = (const float*)d_in[1];
    const float* x_evid   = (const float*)d_in[2];
    const int*   ei       = (const int*)d_in[3];     // [4, 2, E]
    const int*   bidx     = (const int*)d_in[4];     // [B]
    const float* Wl1      = (const float*)d_in[5];   // [4,64,64]
    const float* bl1      = (const float*)d_in[6];   // [4,64]
    const float* Wr1      = (const float*)d_in[7];   // [4,64,64]
    const float* Wl2      = (const float*)d_in[8];
    const float* bl2      = (const float*)d_in[9];
    const float* Wr2      = (const float*)d_in[10];
    const float* Wc       = (const float*)d_in[11];  // [64,2]
    const float* bc       = (const float*)d_in[12];  // [2]
    float* out = (float*)d_out;

    const int E  = in_sizes[3] / 8;
    const int B  = in_sizes[4];
    const int nc = in_sizes[0] / 64;
    const int ne = in_sizes[1] / 64;
    const int nv = in_sizes[2] / 64;

    float *z, *h1c, *h1e, *h1v, *Wr1c, *b1c;
    cudaGetSymbolAddress((void**)&z, g_zero);
    cudaGetSymbolAddress((void**)&h1c, g_h1c);
    cudaGetSymbolAddress((void**)&h1e, g_h1e);
    cudaGetSymbolAddress((void**)&h1v, g_h1v);
    cudaGetSymbolAddress((void**)&Wr1c, g_Wr1c);
    cudaGetSymbolAddress((void**)&b1c, g_b1c);

    float* agg0  = z + O_AGG0;
    float* agg1  = z + O_AGG1;
    float* agg2  = z + O_AGG2;
    float* agg3  = z + O_AGG3;
    float* aggL0 = z + O_AGGL0;
    float* aggL1 = z + O_AGGL1;
    float* cnt0  = z + O_CNT0;
    float* cnt1  = z + O_CNT1;
    float* cnt2  = z + O_CNT2;
    float* cnt3  = z + O_CNT3;

    // prep folded weights + zero all accumulators in one shot
    prep_kernel<<<1, 256>>>(Wr1, bl1, Wl2, bl2, Wr2, Wc, bc);
    cudaMemsetAsync(z, 0, (size_t)ZTOT * sizeof(float));

    const int sthreads = 256;
    const int sblocks = (E * 16 + sthreads - 1) / sthreads;
    const size_t e2 = (size_t)2 * E;

    // ---- layer-1 scatter: all 4 edge types in one grid ----
    SCArgs a1;
    a1.src[0] = (const float4*)x_entity; a1.agg[0] = (float4*)agg0; a1.cnt[0] = cnt0;
    a1.es[0] = ei + 0 * e2; a1.ed[0] = ei + 0 * e2 + E;
    a1.src[1] = (const float4*)x_evid;   a1.agg[1] = (float4*)agg1; a1.cnt[1] = cnt1;
    a1.es[1] = ei + 1 * e2; a1.ed[1] = ei + 1 * e2 + E;
    a1.src[2] = (const float4*)x_claim;  a1.agg[2] = (float4*)agg2; a1.cnt[2] = cnt2;
    a1.es[2] = ei + 2 * e2; a1.ed[2] = ei + 2 * e2 + E;
    a1.src[3] = (const float4*)x_claim;  a1.agg[3] = (float4*)agg3; a1.cnt[3] = cnt3;
    a1.es[3] = ei + 3 * e2; a1.ed[3] = ei + 3 * e2 + E;
    scatter_multi<true><<<dim3(sblocks, 4), sthreads>>>(a1, E);

    // ---- layer-1 transforms (+ReLU) ----
    transform_kernel<2, true><<<(nc + 63) / 64, 256>>>(agg0, cnt0, agg1, cnt1, x_claim,
                                                       Wl1 + 0 * 4096, Wl1 + 1 * 4096, Wr1c, b1c,
                                                       h1c, nc);
    transform_kernel<1, true><<<(ne + 63) / 64, 256>>>(agg2, cnt2, nullptr, nullptr, x_entity,
                                                       Wl1 + 2 * 4096, nullptr, Wr1 + 2 * 4096, bl1 + 128,
                                                       h1e, ne);
    transform_kernel<1, true><<<(nv + 63) / 64, 256>>>(agg3, cnt3, nullptr, nullptr, x_evid,
                                                       Wl1 + 3 * 4096, nullptr, Wr1 + 3 * 4096, bl1 + 192,
                                                       h1v, nv);

    // ---- layer-2 scatter: both claim-destination types in one grid ----
    // counts are identical to layer-1 (same edges) -> reuse cnt0/cnt1
    SCArgs a2;
    a2.src[0] = (const float4*)h1e; a2.agg[0] = (float4*)aggL0; a2.cnt[0] = nullptr;
    a2.es[0] = ei + 0 * e2; a2.ed[0] = ei + 0 * e2 + E;
    a2.src[1] = (const float4*)h1v; a2.agg[1] = (float4*)aggL1; a2.cnt[1] = nullptr;
    a2.es[1] = ei + 1 * e2; a2.ed[1] = ei + 1 * e2 + E;
    a2.src[2] = nullptr; a2.agg[2] = nullptr; a2.cnt[2] = nullptr; a2.es[2] = nullptr; a2.ed[2] = nullptr;
    a2.src[3] = nullptr; a2.agg[3] = nullptr; a2.cnt[3] = nullptr; a2.es[3] = nullptr; a2.ed[3] = nullptr;
    scatter_multi<false><<<dim3(sblocks, 2), sthreads>>>(a2, E);

    // ---- folded layer-2 linear + classifier on batch indices ----
    final_kernel<<<(B + 255) / 256, 256>>>((const float4*)aggL0, cnt0, (const float4*)aggL1, cnt1,
                                           (const float4*)h1c, bidx, out, B);
}

// round 3
// speedup vs baseline: 1.4339x; 1.3815x over previous
#include <cuda_runtime.h>
#include <cstddef>

#define NC 100000
#define NE 200000
#define NV 150000

// ---------------- consolidated zeroed scratch (single memset) ----------------
#define O_AGG0  0
#define O_AGG1  (NC*64)
#define O_AGG2  (2*NC*64)
#define O_AGG3  (2*NC*64 + NE*64)
#define O_AGGL0 (2*NC*64 + NE*64 + NV*64)
#define O_AGGL1 (3*NC*64 + NE*64 + NV*64)
#define O_CNT0  (4*NC*64 + NE*64 + NV*64)
#define O_CNT1  (O_CNT0 + NC)
#define O_CNT2  (O_CNT1 + NC)
#define O_CNT3  (O_CNT2 + NE)
#define ZTOT    (O_CNT3 + NV)

__device__ float g_zero[ZTOT];
__device__ float g_h1c[NC * 64];
__device__ float g_h1e[NE * 64];
__device__ float g_h1v[NV * 64];
__device__ float g_Wr1c[64 * 64];   // Wr1[0] + Wr1[1]
__device__ float g_b1c[64];         // bl1[0] + bl1[1]
__device__ float g_u0[64 * 2];      // Wl2[0] @ Wc
__device__ float g_u1[64 * 2];      // Wl2[1] @ Wc
__device__ float g_ur[64 * 2];      // (Wr2[0]+Wr2[1]) @ Wc
__device__ float g_b2[2];           // (bl2[0]+bl2[1]) @ Wc + bc

// ---------------- tiny weight prep ----------------
__global__ void prep_kernel(const float* __restrict__ Wr1, const float* __restrict__ bl1,
                            const float* __restrict__ Wl2, const float* __restrict__ bl2,
                            const float* __restrict__ Wr2, const float* __restrict__ Wc,
                            const float* __restrict__ bc)
{
    int tid = threadIdx.x;
    for (int idx = tid; idx < 4096; idx += 256)
        g_Wr1c[idx] = Wr1[idx] + Wr1[4096 + idx];
    if (tid < 64) g_b1c[tid] = bl1[tid] + bl1[64 + tid];
    if (tid < 128) {
        int i = tid >> 1, c = tid & 1;
        float s0 = 0.f, s1 = 0.f, sr = 0.f;
        for (int j = 0; j < 64; j++) {
            float wc = Wc[j * 2 + c];
            s0 += Wl2[i * 64 + j] * wc;
            s1 += Wl2[4096 + i * 64 + j] * wc;
            sr += (Wr2[i * 64 + j] + Wr2[4096 + i * 64 + j]) * wc;
        }
        g_u0[tid] = s0; g_u1[tid] = s1; g_ur[tid] = sr;
    }
    if (tid < 2) {
        float s = bc[tid];
        for (int j = 0; j < 64; j++) s += (bl2[j] + bl2[64 + j]) * Wc[j * 2 + tid];
        g_b2[tid] = s;
    }
}

// ---------------- merged multi-type edge scatter (8 threads/edge, 2 float4 each) ----------------
struct SCArgs {
    const float4* src[4];
    float4*       agg[4];
    float*        cnt[4];
    const int*    es[4];
    const int*    ed[4];
};

template <bool COUNT>
__global__ void scatter_multi(SCArgs a, int E)
{
    int ty = blockIdx.y;
    int t = blockIdx.x * blockDim.x + threadIdx.x;
    int e = t >> 3;
    if (e >= E) return;
    int j = t & 7;
    int s = __ldg(a.es[ty] + e);
    int d = __ldg(a.ed[ty] + e);
    const float4* sp = a.src[ty] + (size_t)s * 16 + j;
    float4* p = a.agg[ty] + (size_t)d * 16 + j;
    float4 v0 = __ldg(sp);
    float4 v1 = __ldg(sp + 8);
    asm volatile("red.global.add.v4.f32 [%0], {%1,%2,%3,%4};"
                 :: "l"(p), "f"(v0.x), "f"(v0.y), "f"(v0.z), "f"(v0.w) : "memory");
    asm volatile("red.global.add.v4.f32 [%0], {%1,%2,%3,%4};"
                 :: "l"(p + 8), "f"(v1.x), "f"(v1.y), "f"(v1.z), "f"(v1.w) : "memory");
    if (COUNT && j == 0) atomicAdd(a.cnt[ty] + d, 1.0f);
}

// ---------------- fused mean + (NMEAN+1)-way 64x64 GEMM + bias + ReLU (scalar f32) ----------------
template <int NMEAN, bool RELU>
__global__ __launch_bounds__(256, 4)
void transform_kernel(const float* __restrict__ agg0, const float* __restrict__ cnt0,
                      const float* __restrict__ agg1, const float* __restrict__ cnt1,
                      const float* __restrict__ x,
                      const float* __restrict__ W0, const float* __restrict__ W1,
                      const float* __restrict__ Wr,
                      const float* __restrict__ bias,
                      float* __restrict__ out, int n)
{
    __shared__ __align__(16) float Ws[64][68];
    __shared__ __align__(16) float As[64][68];
    __shared__ float inv0s[64], inv1s[64];
    int tid = threadIdx.x;
    int row0 = blockIdx.x * 64;
    int cg = tid & 15, rg = tid >> 4;
    int c0 = cg * 4, r0 = rg * 4;

    // stage per-row inverse counts once
    if (tid < 64) {
        int row = row0 + tid;
        float i0 = 1.f, i1 = 1.f;
        if (row < n) {
            if (NMEAN >= 1) i0 = 1.0f / fmaxf(cnt0[row], 1.0f);
            if (NMEAN == 2) i1 = 1.0f / fmaxf(cnt1[row], 1.0f);
        }
        inv0s[tid] = i0; inv1s[tid] = i1;
    }

    float acc[4][4];
#pragma unroll
    for (int ci = 0; ci < 4; ci++) {
        float b = bias[c0 + ci];
#pragma unroll
        for (int ri = 0; ri < 4; ri++) acc[ri][ci] = b;
    }
    __syncthreads();

    for (int p = 0; p <= NMEAN; ++p) {
        const float* inp;
        const float* W;
        const float* invs;
        if (p == 0 && NMEAN >= 1)      { inp = agg0; W = W0; invs = inv0s; }
        else if (p == 1 && NMEAN == 2) { inp = agg1; W = W1; invs = inv1s; }
        else                           { inp = x;    W = Wr; invs = nullptr; }

#pragma unroll
        for (int i = 0; i < 16; i++) {
            int idx = tid + i * 256;
            Ws[idx >> 6][idx & 63] = W[idx];
        }
#pragma unroll
        for (int i = 0; i < 16; i++) {
            int idx = tid + i * 256;
            int r = idx >> 6, c = idx & 63;
            int row = row0 + r;
            float v = 0.f;
            if (row < n) {
                v = inp[(size_t)row * 64 + c];
                if (invs) v *= invs[r];
            }
            As[r][c] = v;
        }
        __syncthreads();

#pragma unroll
        for (int k = 0; k < 64; k++) {
            float4 wv = *(const float4*)&Ws[k][c0];
            float a0 = As[r0 + 0][k];
            float a1 = As[r0 + 1][k];
            float a2 = As[r0 + 2][k];
            float a3 = As[r0 + 3][k];
            acc[0][0] += a0 * wv.x; acc[0][1] += a0 * wv.y; acc[0][2] += a0 * wv.z; acc[0][3] += a0 * wv.w;
            acc[1][0] += a1 * wv.x; acc[1][1] += a1 * wv.y; acc[1][2] += a1 * wv.z; acc[1][3] += a1 * wv.w;
            acc[2][0] += a2 * wv.x; acc[2][1] += a2 * wv.y; acc[2][2] += a2 * wv.z; acc[2][3] += a2 * wv.w;
            acc[3][0] += a3 * wv.x; acc[3][1] += a3 * wv.y; acc[3][2] += a3 * wv.z; acc[3][3] += a3 * wv.w;
        }
        __syncthreads();
    }

#pragma unroll
    for (int ri = 0; ri < 4; ri++) {
        int row = row0 + r0 + ri;
        if (row < n) {
            float4 o;
            o.x = RELU ? fmaxf(acc[ri][0], 0.f) : acc[ri][0];
            o.y = RELU ? fmaxf(acc[ri][1], 0.f) : acc[ri][1];
            o.z = RELU ? fmaxf(acc[ri][2], 0.f) : acc[ri][2];
            o.w = RELU ? fmaxf(acc[ri][3], 0.f) : acc[ri][3];
            *(float4*)&out[(size_t)row * 64 + c0] = o;
        }
    }
}

// ---------------- final: folded layer-2 linear + classifier on gathered claims ----------------
__global__ void final_kernel(const float4* __restrict__ agg0, const float* __restrict__ cnt0,
                             const float4* __restrict__ agg1, const float* __restrict__ cnt1,
                             const float4* __restrict__ h1c,
                             const int* __restrict__ bidx,
                             float* __restrict__ out, int B)
{
    int b = blockIdx.x * blockDim.x + threadIdx.x;
    if (b >= B) return;
    int i = __ldg(bidx + b);
    float inv0 = 1.0f / fmaxf(cnt0[i], 1.0f);
    float inv1 = 1.0f / fmaxf(cnt1[i], 1.0f);
    float acc0 = g_b2[0], acc1 = g_b2[1];
#pragma unroll
    for (int q = 0; q < 16; q++) {
        float4 m0 = __ldg(agg0 + (size_t)i * 16 + q);
        float4 m1 = __ldg(agg1 + (size_t)i * 16 + q);
        float4 h  = __ldg(h1c  + (size_t)i * 16 + q);
        float m0a[4] = {m0.x, m0.y, m0.z, m0.w};
        float m1a[4] = {m1.x, m1.y, m1.z, m1.w};
        float ha[4]  = {h.x,  h.y,  h.z,  h.w};
#pragma unroll
        for (int t = 0; t < 4; t++) {
            int k = q * 4 + t;
            acc0 += m0a[t] * inv0 * g_u0[k * 2 + 0]
                  + m1a[t] * inv1 * g_u1[k * 2 + 0]
                  + ha[t]         * g_ur[k * 2 + 0];
            acc1 += m0a[t] * inv0 * g_u0[k * 2 + 1]
                  + m1a[t] * inv1 * g_u1[k * 2 + 1]
                  + ha[t]         * g_ur[k * 2 + 1];
        }
    }
    out[(size_t)b * 2 + 0] = acc0;
    out[(size_t)b * 2 + 1] = acc1;
}

// ---------------- launch ----------------
extern "C" void kernel_launch(void* const* d_in, const int* in_sizes, int n_in,
                              void* d_out, int out_size)
{
    const float* x_claim  = (const float*)d_in[0];
    const float* x_entity = (const float*)d_in[1];
    const float* x_evid   = (const float*)d_in[2];
    const int*   ei       = (const int*)d_in[3];     // [4, 2, E]
    const int*   bidx     = (const int*)d_in[4];     // [B]
    const float* Wl1      = (const float*)d_in[5];   // [4,64,64]
    const float* bl1      = (const float*)d_in[6];   // [4,64]
    const float* Wr1      = (const float*)d_in[7];   // [4,64,64]
    const float* Wl2      = (const float*)d_in[8];
    const float* bl2      = (const float*)d_in[9];
    const float* Wr2      = (const float*)d_in[10];
    const float* Wc       = (const float*)d_in[11];  // [64,2]
    const float* bc       = (const float*)d_in[12];  // [2]
    float* out = (float*)d_out;

    const int E  = in_sizes[3] / 8;
    const int B  = in_sizes[4];
    const int nc = in_sizes[0] / 64;
    const int ne = in_sizes[1] / 64;
    const int nv = in_sizes[2] / 64;

    float *z, *h1c, *h1e, *h1v, *Wr1c, *b1c;
    cudaGetSymbolAddress((void**)&z, g_zero);
    cudaGetSymbolAddress((void**)&h1c, g_h1c);
    cudaGetSymbolAddress((void**)&h1e, g_h1e);
    cudaGetSymbolAddress((void**)&h1v, g_h1v);
    cudaGetSymbolAddress((void**)&Wr1c, g_Wr1c);
    cudaGetSymbolAddress((void**)&b1c, g_b1c);

    float* agg0  = z + O_AGG0;
    float* agg1  = z + O_AGG1;
    float* agg2  = z + O_AGG2;
    float* agg3  = z + O_AGG3;
    float* aggL0 = z + O_AGGL0;
    float* aggL1 = z + O_AGGL1;
    float* cnt0  = z + O_CNT0;
    float* cnt1  = z + O_CNT1;
    float* cnt2  = z + O_CNT2;
    float* cnt3  = z + O_CNT3;

    // prep folded weights + zero all accumulators in one shot
    prep_kernel<<<1, 256>>>(Wr1, bl1, Wl2, bl2, Wr2, Wc, bc);
    cudaMemsetAsync(z, 0, (size_t)ZTOT * sizeof(float));

    const int sthreads = 256;
    const int sblocks = (E * 8 + sthreads - 1) / sthreads;
    const size_t e2 = (size_t)2 * E;

    // ---- layer-1 scatter: all 4 edge types in one grid ----
    SCArgs a1;
    a1.src[0] = (const float4*)x_entity; a1.agg[0] = (float4*)agg0; a1.cnt[0] = cnt0;
    a1.es[0] = ei + 0 * e2; a1.ed[0] = ei + 0 * e2 + E;
    a1.src[1] = (const float4*)x_evid;   a1.agg[1] = (float4*)agg1; a1.cnt[1] = cnt1;
    a1.es[1] = ei + 1 * e2; a1.ed[1] = ei + 1 * e2 + E;
    a1.src[2] = (const float4*)x_claim;  a1.agg[2] = (float4*)agg2; a1.cnt[2] = cnt2;
    a1.es[2] = ei + 2 * e2; a1.ed[2] = ei + 2 * e2 + E;
    a1.src[3] = (const float4*)x_claim;  a1.agg[3] = (float4*)agg3; a1.cnt[3] = cnt3;
    a1.es[3] = ei + 3 * e2; a1.ed[3] = ei + 3 * e2 + E;
    scatter_multi<true><<<dim3(sblocks, 4), sthreads>>>(a1, E);

    // ---- layer-1 transforms (+ReLU) ----
    transform_kernel<2, true><<<(nc + 63) / 64, 256>>>(agg0, cnt0, agg1, cnt1, x_claim,
                                                       Wl1 + 0 * 4096, Wl1 + 1 * 4096, Wr1c, b1c,
                                                       h1c, nc);
    transform_kernel<1, true><<<(ne + 63) / 64, 256>>>(agg2, cnt2, nullptr, nullptr, x_entity,
                                                       Wl1 + 2 * 4096, nullptr, Wr1 + 2 * 4096, bl1 + 128,
                                                       h1e, ne);
    transform_kernel<1, true><<<(nv + 63) / 64, 256>>>(agg3, cnt3, nullptr, nullptr, x_evid,
                                                       Wl1 + 3 * 4096, nullptr, Wr1 + 3 * 4096, bl1 + 192,
                                                       h1v, nv);

    // ---- layer-2 scatter: both claim-destination types in one grid ----
    // counts are identical to layer-1 (same edges) -> reuse cnt0/cnt1
    SCArgs a2;
    a2.src[0] = (const float4*)h1e; a2.agg[0] = (float4*)aggL0; a2.cnt[0] = nullptr;
    a2.es[0] = ei + 0 * e2; a2.ed[0] = ei + 0 * e2 + E;
    a2.src[1] = (const float4*)h1v; a2.agg[1] = (float4*)aggL1; a2.cnt[1] = nullptr;
    a2.es[1] = ei + 1 * e2; a2.ed[1] = ei + 1 * e2 + E;
    a2.src[2] = nullptr; a2.agg[2] = nullptr; a2.cnt[2] = nullptr; a2.es[2] = nullptr; a2.ed[2] = nullptr;
    a2.src[3] = nullptr; a2.agg[3] = nullptr; a2.cnt[3] = nullptr; a2.es[3] = nullptr; a2.ed[3] = nullptr;
    scatter_multi<false><<<dim3(sblocks, 2), sthreads>>>(a2, E);

    // ---- folded layer-2 linear + classifier on batch indices ----
    final_kernel<<<(B + 255) / 256, 256>>>((const float4*)aggL0, cnt0, (const float4*)aggL1, cnt1,
                                           (const float4*)h1c, bidx, out, B);
}

// round 4
// speedup vs baseline: 1.7179x; 1.1981x over previous
#include <cuda_runtime.h>
#include <cstddef>

#define NC 100000
#define NE 200000
#define NV 150000

// ---------------- consolidated zeroed scratch (single memset) ----------------
#define O_AGG0  0
#define O_AGG1  (NC*64)
#define O_AGG2  (2*NC*64)
#define O_AGG3  (2*NC*64 + NE*64)
#define O_AGGP0 (2*NC*64 + NE*64 + NV*64)
#define O_AGGP1 (O_AGGP0 + NC*2)
#define O_CNT0  (O_AGGP1 + NC*2)
#define O_CNT1  (O_CNT0 + NC)
#define O_CNT2  (O_CNT1 + NC)
#define O_CNT3  (O_CNT2 + NE)
#define ZTOT    (O_CNT3 + NV)

__device__ float g_zero[ZTOT];
__device__ float g_pc[NC * 2];      // relu(h1_claim) @ ur
__device__ float g_pe[NE * 2];      // relu(h1_entity) @ u0
__device__ float g_pv[NV * 2];      // relu(h1_evid) @ u1
__device__ float g_Wr1c[64 * 64];   // Wr1[0] + Wr1[1]
__device__ float g_b1c[64];         // bl1[0] + bl1[1]
__device__ float g_u0[64 * 2];      // Wl2[0] @ Wc
__device__ float g_u1[64 * 2];      // Wl2[1] @ Wc
__device__ float g_ur[64 * 2];      // (Wr2[0]+Wr2[1]) @ Wc
__device__ float g_b2[2];           // (bl2[0]+bl2[1]) @ Wc + bc

// ---------------- tiny weight prep ----------------
__global__ void prep_kernel(const float* __restrict__ Wr1, const float* __restrict__ bl1,
                            const float* __restrict__ Wl2, const float* __restrict__ bl2,
                            const float* __restrict__ Wr2, const float* __restrict__ Wc,
                            const float* __restrict__ bc)
{
    int tid = threadIdx.x;
    for (int idx = tid; idx < 4096; idx += 256)
        g_Wr1c[idx] = Wr1[idx] + Wr1[4096 + idx];
    if (tid < 64) g_b1c[tid] = bl1[tid] + bl1[64 + tid];
    if (tid < 128) {
        int i = tid >> 1, c = tid & 1;
        float s0 = 0.f, s1 = 0.f, sr = 0.f;
        for (int j = 0; j < 64; j++) {
            float wc = Wc[j * 2 + c];
            s0 += Wl2[i * 64 + j] * wc;
            s1 += Wl2[4096 + i * 64 + j] * wc;
            sr += (Wr2[i * 64 + j] + Wr2[4096 + i * 64 + j]) * wc;
        }
        g_u0[tid] = s0; g_u1[tid] = s1; g_ur[tid] = sr;
    }
    if (tid < 2) {
        float s = bc[tid];
        for (int j = 0; j < 64; j++) s += (bl2[j] + bl2[64 + j]) * Wc[j * 2 + tid];
        g_b2[tid] = s;
    }
}

// ---------------- layer-1 merged multi-type edge scatter (8 threads/edge) ----------------
struct SCArgs {
    const float4* src[4];
    float4*       agg[4];
    float*        cnt[4];
    const int*    es[4];
    const int*    ed[4];
};

__global__ void scatter_multi(SCArgs a, int E)
{
    int ty = blockIdx.y;
    int t = blockIdx.x * blockDim.x + threadIdx.x;
    int e = t >> 3;
    if (e >= E) return;
    int j = t & 7;
    int s = __ldg(a.es[ty] + e);
    int d = __ldg(a.ed[ty] + e);
    const float4* sp = a.src[ty] + (size_t)s * 16 + j;
    float4* p = a.agg[ty] + (size_t)d * 16 + j;
    float4 v0 = __ldg(sp);
    float4 v1 = __ldg(sp + 8);
    asm volatile("red.global.add.v4.f32 [%0], {%1,%2,%3,%4};"
                 :: "l"(p), "f"(v0.x), "f"(v0.y), "f"(v0.z), "f"(v0.w) : "memory");
    asm volatile("red.global.add.v4.f32 [%0], {%1,%2,%3,%4};"
                 :: "l"(p + 8), "f"(v1.x), "f"(v1.y), "f"(v1.z), "f"(v1.w) : "memory");
    if (j == 0) atomicAdd(a.cnt[ty] + d, 1.0f);
}

// ---------------- layer-2 scatter of 2-dim projections (1 thread/edge) ----------------
struct SPArgs {
    const float2* src[2];
    float2*       agg[2];
    const int*    es[2];
    const int*    ed[2];
};

__global__ void scatter_proj(SPArgs a, int E)
{
    int ty = blockIdx.y;
    int e = blockIdx.x * blockDim.x + threadIdx.x;
    if (e >= E) return;
    int s = __ldg(a.es[ty] + e);
    int d = __ldg(a.ed[ty] + e);
    float2 v = __ldg(a.src[ty] + s);
    float2* p = a.agg[ty] + d;
    asm volatile("red.global.add.v2.f32 [%0], {%1,%2};"
                 :: "l"(p), "f"(v.x), "f"(v.y) : "memory");
}

// ---------------- fused mean + (NMEAN+1)-way 64x64 GEMM + bias + ReLU + 2-dim projection ----------------
template <int NMEAN>
__global__ __launch_bounds__(256, 4)
void transform_kernel(const float* __restrict__ agg0, const float* __restrict__ cnt0,
                      const float* __restrict__ agg1, const float* __restrict__ cnt1,
                      const float* __restrict__ x,
                      const float* __restrict__ W0, const float* __restrict__ W1,
                      const float* __restrict__ Wr,
                      const float* __restrict__ bias,
                      const float* __restrict__ uvec,
                      float2* __restrict__ outp, int n)
{
    __shared__ __align__(16) float Ws[64][68];
    __shared__ __align__(16) float As[64][68];
    __shared__ float inv0s[64], inv1s[64];
    __shared__ float us[128];
    int tid = threadIdx.x;
    int row0 = blockIdx.x * 64;
    int cg = tid & 15, rg = tid >> 4;
    int c0 = cg * 4, r0 = rg * 4;

    if (tid < 128) us[tid] = uvec[tid];
    if (tid >= 128 && tid < 192) {
        int r = tid - 128;
        int row = row0 + r;
        float i0 = 1.f, i1 = 1.f;
        if (row < n) {
            if (NMEAN >= 1) i0 = 1.0f / fmaxf(cnt0[row], 1.0f);
            if (NMEAN == 2) i1 = 1.0f / fmaxf(cnt1[row], 1.0f);
        }
        inv0s[r] = i0; inv1s[r] = i1;
    }

    float acc[4][4];
#pragma unroll
    for (int ci = 0; ci < 4; ci++) {
        float b = bias[c0 + ci];
#pragma unroll
        for (int ri = 0; ri < 4; ri++) acc[ri][ci] = b;
    }
    __syncthreads();

    for (int p = 0; p <= NMEAN; ++p) {
        const float* inp;
        const float* W;
        const float* invs;
        if (p == 0 && NMEAN >= 1)      { inp = agg0; W = W0; invs = inv0s; }
        else if (p == 1 && NMEAN == 2) { inp = agg1; W = W1; invs = inv1s; }
        else                           { inp = x;    W = Wr; invs = nullptr; }

#pragma unroll
        for (int i = 0; i < 16; i++) {
            int idx = tid + i * 256;
            Ws[idx >> 6][idx & 63] = W[idx];
        }
#pragma unroll
        for (int i = 0; i < 16; i++) {
            int idx = tid + i * 256;
            int r = idx >> 6, c = idx & 63;
            int row = row0 + r;
            float v = 0.f;
            if (row < n) {
                v = inp[(size_t)row * 64 + c];
                if (invs) v *= invs[r];
            }
            As[r][c] = v;
        }
        __syncthreads();

#pragma unroll
        for (int k4 = 0; k4 < 16; k4++) {
            float4 a0 = *(const float4*)&As[r0 + 0][k4 * 4];
            float4 a1 = *(const float4*)&As[r0 + 1][k4 * 4];
            float4 a2 = *(const float4*)&As[r0 + 2][k4 * 4];
            float4 a3 = *(const float4*)&As[r0 + 3][k4 * 4];
#pragma unroll
            for (int kk = 0; kk < 4; kk++) {
                float4 wv = *(const float4*)&Ws[k4 * 4 + kk][c0];
                float f0 = (&a0.x)[kk];
                float f1 = (&a1.x)[kk];
                float f2 = (&a2.x)[kk];
                float f3 = (&a3.x)[kk];
                acc[0][0] += f0 * wv.x; acc[0][1] += f0 * wv.y; acc[0][2] += f0 * wv.z; acc[0][3] += f0 * wv.w;
                acc[1][0] += f1 * wv.x; acc[1][1] += f1 * wv.y; acc[1][2] += f1 * wv.z; acc[1][3] += f1 * wv.w;
                acc[2][0] += f2 * wv.x; acc[2][1] += f2 * wv.y; acc[2][2] += f2 * wv.z; acc[2][3] += f2 * wv.w;
                acc[3][0] += f3 * wv.x; acc[3][1] += f3 * wv.y; acc[3][2] += f3 * wv.z; acc[3][3] += f3 * wv.w;
            }
        }
        __syncthreads();
    }

    // write relu(h1) back to As, then project to 2 dims with uvec
#pragma unroll
    for (int ri = 0; ri < 4; ri++)
#pragma unroll
        for (int ci = 0; ci < 4; ci++)
            As[r0 + ri][c0 + ci] = fmaxf(acc[ri][ci], 0.f);
    __syncthreads();

    if (tid < 64) {
        int row = row0 + tid;
        if (row < n) {
            float s0 = 0.f, s1 = 0.f;
#pragma unroll
            for (int k = 0; k < 64; k++) {
                float v = As[tid][k];
                s0 += v * us[2 * k + 0];
                s1 += v * us[2 * k + 1];
            }
            outp[row] = make_float2(s0, s1);
        }
    }
}

// ---------------- final: combine 2-dim pieces on gathered claims ----------------
__global__ void final_kernel(const float2* __restrict__ aggP0, const float* __restrict__ cnt0,
                             const float2* __restrict__ aggP1, const float* __restrict__ cnt1,
                             const float2* __restrict__ pc,
                             const int* __restrict__ bidx,
                             float2* __restrict__ out, int B)
{
    int b = blockIdx.x * blockDim.x + threadIdx.x;
    if (b >= B) return;
    int i = __ldg(bidx + b);
    float inv0 = 1.0f / fmaxf(cnt0[i], 1.0f);
    float inv1 = 1.0f / fmaxf(cnt1[i], 1.0f);
    float2 a0 = __ldg(aggP0 + i);
    float2 a1 = __ldg(aggP1 + i);
    float2 c  = __ldg(pc + i);
    float2 o;
    o.x = g_b2[0] + a0.x * inv0 + a1.x * inv1 + c.x;
    o.y = g_b2[1] + a0.y * inv0 + a1.y * inv1 + c.y;
    out[b] = o;
}

// ---------------- launch ----------------
extern "C" void kernel_launch(void* const* d_in, const int* in_sizes, int n_in,
                              void* d_out, int out_size)
{
    const float* x_claim  = (const float*)d_in[0];
    const float* x_entity = (const float*)d_in[1];
    const float* x_evid   = (const float*)d_in[2];
    const int*   ei       = (const int*)d_in[3];     // [4, 2, E]
    const int*   bidx     = (const int*)d_in[4];     // [B]
    const float* Wl1      = (const float*)d_in[5];   // [4,64,64]
    const float* bl1      = (const float*)d_in[6];   // [4,64]
    const float* Wr1      = (const float*)d_in[7];   // [4,64,64]
    const float* Wl2      = (const float*)d_in[8];
    const float* bl2      = (const float*)d_in[9];
    const float* Wr2      = (const float*)d_in[10];
    const float* Wc       = (const float*)d_in[11];  // [64,2]
    const float* bc       = (const float*)d_in[12];  // [2]
    float2* out = (float2*)d_out;

    const int E  = in_sizes[3] / 8;
    const int B  = in_sizes[4];
    const int nc = in_sizes[0] / 64;
    const int ne = in_sizes[1] / 64;
    const int nv = in_sizes[2] / 64;

    float *z, *pc, *pe, *pv, *Wr1c, *b1c, *u0, *u1, *ur;
    cudaGetSymbolAddress((void**)&z, g_zero);
    cudaGetSymbolAddress((void**)&pc, g_pc);
    cudaGetSymbolAddress((void**)&pe, g_pe);
    cudaGetSymbolAddress((void**)&pv, g_pv);
    cudaGetSymbolAddress((void**)&Wr1c, g_Wr1c);
    cudaGetSymbolAddress((void**)&b1c, g_b1c);
    cudaGetSymbolAddress((void**)&u0, g_u0);
    cudaGetSymbolAddress((void**)&u1, g_u1);
    cudaGetSymbolAddress((void**)&ur, g_ur);

    float* agg0  = z + O_AGG0;
    float* agg1  = z + O_AGG1;
    float* agg2  = z + O_AGG2;
    float* agg3  = z + O_AGG3;
    float* aggP0 = z + O_AGGP0;
    float* aggP1 = z + O_AGGP1;
    float* cnt0  = z + O_CNT0;
    float* cnt1  = z + O_CNT1;
    float* cnt2  = z + O_CNT2;
    float* cnt3  = z + O_CNT3;

    prep_kernel<<<1, 256>>>(Wr1, bl1, Wl2, bl2, Wr2, Wc, bc);
    cudaMemsetAsync(z, 0, (size_t)ZTOT * sizeof(float));

    const int sthreads = 256;
    const int sblocks = (E * 8 + sthreads - 1) / sthreads;
    const size_t e2 = (size_t)2 * E;

    // ---- layer-1 scatter: all 4 edge types ----
    SCArgs a1;
    a1.src[0] = (const float4*)x_entity; a1.agg[0] = (float4*)agg0; a1.cnt[0] = cnt0;
    a1.es[0] = ei + 0 * e2; a1.ed[0] = ei + 0 * e2 + E;
    a1.src[1] = (const float4*)x_evid;   a1.agg[1] = (float4*)agg1; a1.cnt[1] = cnt1;
    a1.es[1] = ei + 1 * e2; a1.ed[1] = ei + 1 * e2 + E;
    a1.src[2] = (const float4*)x_claim;  a1.agg[2] = (float4*)agg2; a1.cnt[2] = cnt2;
    a1.es[2] = ei + 2 * e2; a1.ed[2] = ei + 2 * e2 + E;
    a1.src[3] = (const float4*)x_claim;  a1.agg[3] = (float4*)agg3; a1.cnt[3] = cnt3;
    a1.es[3] = ei + 3 * e2; a1.ed[3] = ei + 3 * e2 + E;
    scatter_multi<<<dim3(sblocks, 4), sthreads>>>(a1, E);

    // ---- layer-1 transforms -> 2-dim projections ----
    transform_kernel<2><<<(nc + 63) / 64, 256>>>(agg0, cnt0, agg1, cnt1, x_claim,
                                                 Wl1 + 0 * 4096, Wl1 + 1 * 4096, Wr1c, b1c,
                                                 ur, (float2*)pc, nc);
    transform_kernel<1><<<(ne + 63) / 64, 256>>>(agg2, cnt2, nullptr, nullptr, x_entity,
                                                 Wl1 + 2 * 4096, nullptr, Wr1 + 2 * 4096, bl1 + 128,
                                                 u0, (float2*)pe, ne);
    transform_kernel<1><<<(nv + 63) / 64, 256>>>(agg3, cnt3, nullptr, nullptr, x_evid,
                                                 Wl1 + 3 * 4096, nullptr, Wr1 + 3 * 4096, bl1 + 192,
                                                 u1, (float2*)pv, nv);

    // ---- layer-2 scatter on 2-dim projections (counts reuse cnt0/cnt1) ----
    SPArgs a2;
    a2.src[0] = (const float2*)pe; a2.agg[0] = (float2*)aggP0;
    a2.es[0] = ei + 0 * e2; a2.ed[0] = ei + 0 * e2 + E;
    a2.src[1] = (const float2*)pv; a2.agg[1] = (float2*)aggP1;
    a2.es[1] = ei + 1 * e2; a2.ed[1] = ei + 1 * e2 + E;
    scatter_proj<<<dim3((E + 255) / 256, 2), 256>>>(a2, E);

    // ---- final combine ----
    final_kernel<<<(B + 255) / 256, 256>>>((const float2*)aggP0, cnt0, (const float2*)aggP1, cnt1,
                                           (const float2*)pc, bidx, out, B);
}

// round 9
// speedup vs baseline: 1.8207x; 1.0598x over previous
#include <cuda_runtime.h>
#include <cstddef>

#define NC 100000
#define NE 200000
#define NV 150000
#define NTOT (2*NC + NE + NV)            // 550000 counters (type-concatenated)
#define SCAN_BLK 256
#define SCAN_ITEMS 16
#define SCAN_TILE (SCAN_BLK*SCAN_ITEMS)  // 4096
#define NSCAN ((NTOT + SCAN_TILE - 1)/SCAN_TILE)

// ---------------- scratch (static device globals) ----------------
__device__ int   g_cnt[NTOT];      // zeroed per run
__device__ float g_aggP[NC * 4];   // zeroed per run: aggP0 | aggP1 (2 floats each)
__device__ int   g_rowstart[NTOT];
__device__ int   g_cursor[NTOT];
__device__ int   g_bsum[NSCAN];
__device__ int   g_csr[4 * 2000000];
__device__ float g_pc[NC * 2];     // relu(h1_claim) @ ur
__device__ float g_pe[NE * 2];     // relu(h1_entity) @ u0
__device__ float g_pv[NV * 2];     // relu(h1_evid) @ u1
__device__ float g_Wr1c[64 * 64];  // Wr1[0] + Wr1[1]
__device__ float g_b1c[64];        // bl1[0] + bl1[1]
__device__ float g_u0[128];        // Wl2[0] @ Wc
__device__ float g_u1[128];        // Wl2[1] @ Wc
__device__ float g_ur[128];        // (Wr2[0]+Wr2[1]) @ Wc
__device__ float g_b2[2];          // (bl2[0]+bl2[1]) @ Wc + bc

__device__ __forceinline__ int type_off(int t) {
    return (t == 0) ? 0 : (t == 1) ? NC : (t == 2) ? 2 * NC : 2 * NC + NE;
}

// ---------------- tiny weight prep ----------------
__global__ void prep_kernel(const float* __restrict__ Wr1, const float* __restrict__ bl1,
                            const float* __restrict__ Wl2, const float* __restrict__ bl2,
                            const float* __restrict__ Wr2, const float* __restrict__ Wc,
                            const float* __restrict__ bc)
{
    int tid = threadIdx.x;
    for (int idx = tid; idx < 4096; idx += 256)
        g_Wr1c[idx] = Wr1[idx] + Wr1[4096 + idx];
    if (tid < 64) g_b1c[tid] = bl1[tid] + bl1[64 + tid];
    if (tid < 128) {
        int i = tid >> 1, c = tid & 1;
        float s0 = 0.f, s1 = 0.f, sr = 0.f;
        for (int j = 0; j < 64; j++) {
            float wc = Wc[j * 2 + c];
            s0 += Wl2[i * 64 + j] * wc;
            s1 += Wl2[4096 + i * 64 + j] * wc;
            sr += (Wr2[i * 64 + j] + Wr2[4096 + i * 64 + j]) * wc;
        }
        g_u0[tid] = s0; g_u1[tid] = s1; g_ur[tid] = sr;
    }
    if (tid < 2) {
        float s = bc[tid];
        for (int j = 0; j < 64; j++) s += (bl2[j] + bl2[64 + j]) * Wc[j * 2 + tid];
        g_b2[tid] = s;
    }
}

// ---------------- CSR build: histogram / scan / permute ----------------
__global__ void hist_kernel(const int* __restrict__ ei, int E)
{
    int t = blockIdx.y;
    int e = blockIdx.x * blockDim.x + threadIdx.x;
    if (e >= E) return;
    const int* dst = ei + (size_t)(2 * t + 1) * E;
    atomicAdd(&g_cnt[type_off(t) + __ldg(dst + e)], 1);
}

__global__ void scan1_kernel()
{
    __shared__ int s[SCAN_BLK];
    int base = blockIdx.x * SCAN_TILE + threadIdx.x * SCAN_ITEMS;
    int sum = 0;
#pragma unroll
    for (int i = 0; i < SCAN_ITEMS; i++) {
        int idx = base + i;
        if (idx < NTOT) sum += g_cnt[idx];
    }
    s[threadIdx.x] = sum;
    __syncthreads();
    for (int o = SCAN_BLK / 2; o > 0; o >>= 1) {
        if (threadIdx.x < o) s[threadIdx.x] += s[threadIdx.x + o];
        __syncthreads();
    }
    if (threadIdx.x == 0) g_bsum[blockIdx.x] = s[0];
}

__global__ void scan2_kernel()
{
    if (threadIdx.x == 0) {
        int acc = 0;
        for (int i = 0; i < NSCAN; i++) { int v = g_bsum[i]; g_bsum[i] = acc; acc += v; }
    }
}

__global__ void scan3_kernel()
{
    __shared__ int s[SCAN_BLK];
    int tid = threadIdx.x;
    int base = blockIdx.x * SCAN_TILE + tid * SCAN_ITEMS;
    int local[SCAN_ITEMS];
    int sum = 0;
#pragma unroll
    for (int i = 0; i < SCAN_ITEMS; i++) {
        int idx = base + i;
        int v = (idx < NTOT) ? g_cnt[idx] : 0;
        local[i] = sum;
        sum += v;
    }
    s[tid] = sum;
    __syncthreads();
    for (int o = 1; o < SCAN_BLK; o <<= 1) {
        int v = 0;
        if (tid >= o) v = s[tid - o];
        __syncthreads();
        s[tid] += v;
        __syncthreads();
    }
    int texcl = (tid == 0) ? 0 : s[tid - 1];
    int boff = g_bsum[blockIdx.x];
#pragma unroll
    for (int i = 0; i < SCAN_ITEMS; i++) {
        int idx = base + i;
        if (idx < NTOT) {
            int v = boff + texcl + local[i];
            g_rowstart[idx] = v;
            g_cursor[idx] = v;
        }
    }
}

__global__ void permute_kernel(const int* __restrict__ ei, int E)
{
    int t = blockIdx.y;
    int e = blockIdx.x * blockDim.x + threadIdx.x;
    if (e >= E) return;
    const int* src = ei + (size_t)(2 * t) * E;
    const int* dst = src + E;
    int d = __ldg(dst + e);
    int pos = atomicAdd(&g_cursor[type_off(t) + d], 1);
    g_csr[pos] = __ldg(src + e);
}

// ---------------- fused CSR-gather mean + GEMM + bias + ReLU + 2-dim projection ----------------
template <int NMEAN>
__global__ __launch_bounds__(256, 4)
void transform_fused(const float2* __restrict__ xs0, const int* __restrict__ rs0, const int* __restrict__ cn0,
                     const float2* __restrict__ xs1, const int* __restrict__ rs1, const int* __restrict__ cn1,
                     const float* __restrict__ x,
                     const float* __restrict__ W0, const float* __restrict__ W1,
                     const float* __restrict__ Wr,
                     const float* __restrict__ bias,
                     const float* __restrict__ uvec,
                     float2* __restrict__ outp, int n)
{
    __shared__ __align__(16) float Ws[64][68];
    __shared__ __align__(16) float As[64][68];
    __shared__ float us[128];
    int tid = threadIdx.x;
    int row0 = blockIdx.x * 64;
    int cg = tid & 15, rg = tid >> 4;
    int c0 = cg * 4, r0 = rg * 4;
    int lane = tid & 31, wrp = tid >> 5;

    if (tid < 128) us[tid] = uvec[tid];

    float acc[4][4];
#pragma unroll
    for (int ci = 0; ci < 4; ci++) {
        float b = bias[c0 + ci];
#pragma unroll
        for (int ri = 0; ri < 4; ri++) acc[ri][ci] = b;
    }

    for (int p = 0; p <= NMEAN; ++p) {
        const float* W = (p == 0 && NMEAN >= 1) ? W0
                       : (p == 1 && NMEAN == 2) ? W1 : Wr;
#pragma unroll
        for (int i = 0; i < 16; i++) {
            int idx = tid + i * 256;
            Ws[idx >> 6][idx & 63] = W[idx];
        }

        if (p < NMEAN) {
            // CSR-gather mean: warp per 8 rows, lane = column pair
            const float2* xs = (p == 0) ? xs0 : xs1;
            const int* rs = (p == 0) ? rs0 : rs1;
            const int* cn = (p == 0) ? cn0 : cn1;
#pragma unroll 1
            for (int rr = 0; rr < 8; rr++) {
                int r = wrp * 8 + rr;
                int row = row0 + r;
                float ax = 0.f, ay = 0.f;
                float inv = 1.f;
                if (row < n) {
                    int start = __ldg(rs + row);
                    int c = __ldg(cn + row);
                    inv = 1.0f / fmaxf((float)c, 1.0f);
#pragma unroll 4
                    for (int j = 0; j < c; j++) {
                        int sidx = __ldg(&g_csr[start + j]);
                        float2 v = __ldg(xs + (size_t)sidx * 32 + lane);
                        ax += v.x; ay += v.y;
                    }
                }
                *(float2*)&As[r][lane * 2] = make_float2(ax * inv, ay * inv);
            }
        } else {
            // root features: coalesced direct fill
#pragma unroll
            for (int i = 0; i < 16; i++) {
                int idx = tid + i * 256;
                int r = idx >> 6, c = idx & 63;
                int row = row0 + r;
                As[r][c] = (row < n) ? x[(size_t)row * 64 + c] : 0.f;
            }
        }
        __syncthreads();

#pragma unroll
        for (int k4 = 0; k4 < 16; k4++) {
            float4 a0 = *(const float4*)&As[r0 + 0][k4 * 4];
            float4 a1 = *(const float4*)&As[r0 + 1][k4 * 4];
            float4 a2 = *(const float4*)&As[r0 + 2][k4 * 4];
            float4 a3 = *(const float4*)&As[r0 + 3][k4 * 4];
#pragma unroll
            for (int kk = 0; kk < 4; kk++) {
                float4 wv = *(const float4*)&Ws[k4 * 4 + kk][c0];
                float f0 = (&a0.x)[kk];
                float f1 = (&a1.x)[kk];
                float f2 = (&a2.x)[kk];
                float f3 = (&a3.x)[kk];
                acc[0][0] += f0 * wv.x; acc[0][1] += f0 * wv.y; acc[0][2] += f0 * wv.z; acc[0][3] += f0 * wv.w;
                acc[1][0] += f1 * wv.x; acc[1][1] += f1 * wv.y; acc[1][2] += f1 * wv.z; acc[1][3] += f1 * wv.w;
                acc[2][0] += f2 * wv.x; acc[2][1] += f2 * wv.y; acc[2][2] += f2 * wv.z; acc[2][3] += f2 * wv.w;
                acc[3][0] += f3 * wv.x; acc[3][1] += f3 * wv.y; acc[3][2] += f3 * wv.z; acc[3][3] += f3 * wv.w;
            }
        }
        __syncthreads();
    }

    // relu(h1) -> As, then project to 2 dims with uvec
#pragma unroll
    for (int ri = 0; ri < 4; ri++)
#pragma unroll
        for (int ci = 0; ci < 4; ci++)
            As[r0 + ri][c0 + ci] = fmaxf(acc[ri][ci], 0.f);
    __syncthreads();

    if (tid < 64) {
        int row = row0 + tid;
        if (row < n) {
            float s0 = 0.f, s1 = 0.f;
#pragma unroll
            for (int k = 0; k < 64; k++) {
                float v = As[tid][k];
                s0 += v * us[2 * k + 0];
                s1 += v * us[2 * k + 1];
            }
            outp[row] = make_float2(s0, s1);
        }
    }
}

// ---------------- layer-2 scatter of 2-dim projections (1 thread/edge) ----------------
struct SPArgs {
    const float2* src[2];
    float2*       agg[2];
    const int*    es[2];
    const int*    ed[2];
};

__global__ void scatter_proj(SPArgs a, int E)
{
    int ty = blockIdx.y;
    int e = blockIdx.x * blockDim.x + threadIdx.x;
    if (e >= E) return;
    int s = __ldg(a.es[ty] + e);
    int d = __ldg(a.ed[ty] + e);
    float2 v = __ldg(a.src[ty] + s);
    float2* p = a.agg[ty] + d;
    asm volatile("red.global.add.v2.f32 [%0], {%1,%2};"
                 :: "l"(p), "f"(v.x), "f"(v.y) : "memory");
}

// ---------------- final: combine 2-dim pieces on gathered claims ----------------
__global__ void final_kernel(const float2* __restrict__ aggP0, const int* __restrict__ cn0,
                             const float2* __restrict__ aggP1, const int* __restrict__ cn1,
                             const float2* __restrict__ pc,
                             const int* __restrict__ bidx,
                             float2* __restrict__ out, int B)
{
    int b = blockIdx.x * blockDim.x + threadIdx.x;
    if (b >= B) return;
    int i = __ldg(bidx + b);
    float inv0 = 1.0f / fmaxf((float)__ldg(cn0 + i), 1.0f);
    float inv1 = 1.0f / fmaxf((float)__ldg(cn1 + i), 1.0f);
    float2 a0 = __ldg(aggP0 + i);
    float2 a1 = __ldg(aggP1 + i);
    float2 c  = __ldg(pc + i);
    float2 o;
    o.x = g_b2[0] + a0.x * inv0 + a1.x * inv1 + c.x;
    o.y = g_b2[1] + a0.y * inv0 + a1.y * inv1 + c.y;
    out[b] = o;
}

// ---------------- launch ----------------
extern "C" void kernel_launch(void* const* d_in, const int* in_sizes, int n_in,
                              void* d_out, int out_size)
{
    const float* x_claim  = (const float*)d_in[0];
    const float* x_entity = (const float*)d_in[1];
    const float* x_evid   = (const float*)d_in[2];
    const int*   ei       = (const int*)d_in[3];     // [4, 2, E]
    const int*   bidx     = (const int*)d_in[4];     // [B]
    const float* Wl1      = (const float*)d_in[5];   // [4,64,64]
    const float* bl1      = (const float*)d_in[6];   // [4,64]
    const float* Wr1      = (const float*)d_in[7];   // [4,64,64]
    const float* Wl2      = (const float*)d_in[8];
    const float* bl2      = (const float*)d_in[9];
    const float* Wr2      = (const float*)d_in[10];
    const float* Wc       = (const float*)d_in[11];  // [64,2]
    const float* bc       = (const float*)d_in[12];  // [2]
    float2* out = (float2*)d_out;

    const int E  = in_sizes[3] / 8;
    const int B  = in_sizes[4];
    const int nc = in_sizes[0] / 64;
    const int ne = in_sizes[1] / 64;
    const int nv = in_sizes[2] / 64;

    int *cnt, *rowstart;
    float *aggP, *pc, *pe, *pv, *Wr1c, *b1c, *u0, *u1, *ur;
    cudaGetSymbolAddress((void**)&cnt, g_cnt);
    cudaGetSymbolAddress((void**)&rowstart, g_rowstart);
    cudaGetSymbolAddress((void**)&aggP, g_aggP);
    cudaGetSymbolAddress((void**)&pc, g_pc);
    cudaGetSymbolAddress((void**)&pe, g_pe);
    cudaGetSymbolAddress((void**)&pv, g_pv);
    cudaGetSymbolAddress((void**)&Wr1c, g_Wr1c);
    cudaGetSymbolAddress((void**)&b1c, g_b1c);
    cudaGetSymbolAddress((void**)&u0, g_u0);
    cudaGetSymbolAddress((void**)&u1, g_u1);
    cudaGetSymbolAddress((void**)&ur, g_ur);

    prep_kernel<<<1, 256>>>(Wr1, bl1, Wl2, bl2, Wr2, Wc, bc);
    cudaMemsetAsync(cnt, 0, (size_t)NTOT * sizeof(int));
    cudaMemsetAsync(aggP, 0, (size_t)NC * 4 * sizeof(float));

    const int eblk = (E + 255) / 256;

    // ---- CSR build ----
    hist_kernel<<<dim3(eblk, 4), 256>>>(ei, E);
    scan1_kernel<<<NSCAN, SCAN_BLK>>>();
    scan2_kernel<<<1, 32>>>();
    scan3_kernel<<<NSCAN, SCAN_BLK>>>();
    permute_kernel<<<dim3(eblk, 4), 256>>>(ei, E);

    // ---- fused gather-mean + transform -> 2-dim projections ----
    const int* cn0 = cnt;                 const int* rs0 = rowstart;               // entity->claim
    const int* cn1 = cnt + NC;            const int* rs1 = rowstart + NC;          // evidence->claim
    const int* cnE = cnt + 2 * NC;        const int* rsE = rowstart + 2 * NC;      // claim->entity
    const int* cnV = cnt + 2 * NC + NE;   const int* rsV = rowstart + 2 * NC + NE; // claim->evidence

    transform_fused<2><<<(nc + 63) / 64, 256>>>((const float2*)x_entity, rs0, cn0,
                                                (const float2*)x_evid,   rs1, cn1,
                                                x_claim,
                                                Wl1 + 0 * 4096, Wl1 + 1 * 4096, Wr1c, b1c,
                                                ur, (float2*)pc, nc);
    transform_fused<1><<<(ne + 63) / 64, 256>>>((const float2*)x_claim, rsE, cnE,
                                                nullptr, nullptr, nullptr,
                                                x_entity,
                                                Wl1 + 2 * 4096, nullptr, Wr1 + 2 * 4096, bl1 + 128,
                                                u0, (float2*)pe, ne);
    transform_fused<1><<<(nv + 63) / 64, 256>>>((const float2*)x_claim, rsV, cnV,
                                                nullptr, nullptr, nullptr,
                                                x_evid,
                                                Wl1 + 3 * 4096, nullptr, Wr1 + 3 * 4096, bl1 + 192,
                                                u1, (float2*)pv, nv);

    // ---- layer-2 scatter on 2-dim projections ----
    const size_t e2 = (size_t)2 * E;
    SPArgs a2;
    a2.src[0] = (const float2*)pe; a2.agg[0] = (float2*)aggP;
    a2.es[0] = ei + 0 * e2; a2.ed[0] = ei + 0 * e2 + E;
    a2.src[1] = (const float2*)pv; a2.agg[1] = (float2*)(aggP + 2 * NC);
    a2.es[1] = ei + 1 * e2; a2.ed[1] = ei + 1 * e2 + E;
    scatter_proj<<<dim3(eblk, 2), 256>>>(a2, E);

    // ---- final combine ----
    final_kernel<<<(B + 255) / 256, 256>>>((const float2*)aggP, cn0,
                                           (const float2*)(aggP + 2 * NC), cn1,
                                           (const float2*)pc, bidx, out, B);
}